// round 6
// baseline (speedup 1.0000x reference)
#include <cuda_runtime.h>
#include <cuda_bf16.h>

// CrossNetwork (DCN-v1), closed form:
//   x_i = c_i * input + d_i
//   d_{i+1} = d_i + b_i ; e_i = d_i.w_i ; S_i = input.w_i (per-row)
//   c_{i+1} = c_i*(1+S_i) + e_i, c_0 = 1 ; out = c_L*input + d_L
//
// R5 (retry; previous submission hit a container-infra failure, not a kernel
// failure): 3-stage butterfly + lane-select (20 shfl/warp vs 30), float4
// uniform-LDS cross-warp combine (no combine shuffles), software-pipelined
// single barrier (next row's dots/reduce overlap the deferred bar.sync).

#define D    1024
#define L    6
#define TPB  128
#define NW   (TPB / 32)      // 4 warps; red layout: [parity][l*NW + w]

__device__ __forceinline__ float pick6(const float a[L], int i) {
    float s = a[0];
    s = (i == 1) ? a[1] : s;
    s = (i == 2) ? a[2] : s;
    s = (i == 3) ? a[3] : s;
    s = (i == 4) ? a[4] : s;
    s = (i == 5) ? a[5] : s;
    return s;
}

__global__ void __launch_bounds__(TPB, 5) cross_fused(const float* __restrict__ input,
                                                      const float* __restrict__ W,
                                                      const float* __restrict__ b,
                                                      float* __restrict__ out,
                                                      int B) {
    const int t = threadIdx.x;
    const int lane = t & 31, warp = t >> 5;
    const unsigned FULL = 0xFFFFFFFFu;

    // [parity][layer*NW + warp], 16B-aligned per layer for float4 combine reads
    __shared__ __align__(16) float red[2][L * NW];

    // ---- W slice for this thread's 8 columns ----
    float4 wa[L], wb[L];
    #pragma unroll
    for (int l = 0; l < L; ++l) {
        wa[l] = __ldg(reinterpret_cast<const float4*>(W + l * D) + 2 * t);
        wb[l] = __ldg(reinterpret_cast<const float4*>(W + l * D) + 2 * t + 1);
    }

    // ---- Per-CTA prologue: d_L and e_l ----
    float4 da = make_float4(0.f, 0.f, 0.f, 0.f);
    float4 db = make_float4(0.f, 0.f, 0.f, 0.f);
    float pe[L];
    #pragma unroll
    for (int l = 0; l < L; ++l) {
        pe[l] = da.x * wa[l].x + da.y * wa[l].y + da.z * wa[l].z + da.w * wa[l].w
              + db.x * wb[l].x + db.y * wb[l].y + db.z * wb[l].z + db.w * wb[l].w;
        float4 ba = __ldg(reinterpret_cast<const float4*>(b + l * D) + 2 * t);
        float4 bb = __ldg(reinterpret_cast<const float4*>(b + l * D) + 2 * t + 1);
        da.x += ba.x; da.y += ba.y; da.z += ba.z; da.w += ba.w;
        db.x += bb.x; db.y += bb.y; db.z += bb.z; db.w += bb.w;
    }
    // full butterfly for e (runs once; simplicity over speed)
    #pragma unroll
    for (int l = 0; l < L; ++l) {
        #pragma unroll
        for (int o = 16; o > 0; o >>= 1) pe[l] += __shfl_xor_sync(FULL, pe[l], o);
        if (lane == 0) red[0][l * NW + warp] = pe[l];
    }
    __syncthreads();
    float e[L];
    #pragma unroll
    for (int l = 0; l < L; ++l) {
        float4 q = *reinterpret_cast<const float4*>(&red[0][l * NW]);
        e[l] = (q.x + q.y) + (q.z + q.w);
    }
    __syncthreads();   // protect red[0] before loop reuse

    // ---- Grid-stride row loop, software-pipelined ----
    const float4* in4  = reinterpret_cast<const float4*>(input);
    float4*       out4 = reinterpret_cast<float4*>(out);
    const int stride = gridDim.x;
    const int D4 = D / 4;

    int row = blockIdx.x;
    if (row >= B) return;

    float4 xa = in4[(size_t)row * D4 + 2 * t];
    float4 xb = in4[(size_t)row * D4 + 2 * t + 1];

    // --- pre-loop: dots + reduce + STS for row0 into buffer 0 ---
    {
        float acc[L];
        #pragma unroll
        for (int l = 0; l < L; ++l)
            acc[l] = xa.x * wa[l].x + xa.y * wa[l].y + xa.z * wa[l].z + xa.w * wa[l].w
                   + xb.x * wb[l].x + xb.y * wb[l].y + xb.z * wb[l].z + xb.w * wb[l].w;
        #pragma unroll
        for (int l = 0; l < L; ++l) {
            acc[l] += __shfl_xor_sync(FULL, acc[l], 16);
            acc[l] += __shfl_xor_sync(FULL, acc[l], 8);
            acc[l] += __shfl_xor_sync(FULL, acc[l], 4);
        }
        float v = pick6(acc, lane >> 2);             // lane j: layer j>>2, class j&3
        v += __shfl_xor_sync(FULL, v, 1);
        v += __shfl_xor_sync(FULL, v, 2);            // group 4l holds S_l
        if (lane < L * 4 && (lane & 3) == 0)
            red[0][(lane >> 2) * NW + warp] = v;
    }

    int p = 0;
    for (; row < B; row += stride, p ^= 1) {
        const int nrow = row + stride;
        float4 na, nb;
        if (nrow < B) {
            na = in4[(size_t)nrow * D4 + 2 * t];
            nb = in4[(size_t)nrow * D4 + 2 * t + 1];
        }

        __syncthreads();    // partials(row) in red[p] now visible (deferred block)

        // ---- independent work first: next row's dots/reduce/STS into red[p^1] ----
        if (nrow < B) {
            float acc[L];
            #pragma unroll
            for (int l = 0; l < L; ++l)
                acc[l] = na.x * wa[l].x + na.y * wa[l].y + na.z * wa[l].z + na.w * wa[l].w
                       + nb.x * wb[l].x + nb.y * wb[l].y + nb.z * wb[l].z + nb.w * wb[l].w;
            #pragma unroll
            for (int l = 0; l < L; ++l) {
                acc[l] += __shfl_xor_sync(FULL, acc[l], 16);
                acc[l] += __shfl_xor_sync(FULL, acc[l], 8);
                acc[l] += __shfl_xor_sync(FULL, acc[l], 4);
            }
            float v = pick6(acc, lane >> 2);
            v += __shfl_xor_sync(FULL, v, 1);
            v += __shfl_xor_sync(FULL, v, 2);
            if (lane < L * 4 && (lane & 3) == 0)
                red[p ^ 1][(lane >> 2) * NW + warp] = v;
        }

        // ---- dependent: combine row's partials (uniform float4 LDS, no shfl) ----
        float c = 1.0f;
        #pragma unroll
        for (int l = 0; l < L; ++l) {
            float4 q = *reinterpret_cast<const float4*>(&red[p][l * NW]);
            float S = (q.x + q.y) + (q.z + q.w);
            c = fmaf(c, 1.0f + S, e[l]);
        }

        float4 oa, ob;
        oa.x = fmaf(c, xa.x, da.x); oa.y = fmaf(c, xa.y, da.y);
        oa.z = fmaf(c, xa.z, da.z); oa.w = fmaf(c, xa.w, da.w);
        ob.x = fmaf(c, xb.x, db.x); ob.y = fmaf(c, xb.y, db.y);
        ob.z = fmaf(c, xb.z, db.z); ob.w = fmaf(c, xb.w, db.w);
        out4[(size_t)row * D4 + 2 * t]     = oa;
        out4[(size_t)row * D4 + 2 * t + 1] = ob;

        xa = na; xb = nb;
    }
}

extern "C" void kernel_launch(void* const* d_in, const int* in_sizes, int n_in,
                              void* d_out, int out_size) {
    const float* input = (const float*)d_in[0];   // [B, D]
    const float* W     = (const float*)d_in[1];   // [L, D]
    const float* b     = (const float*)d_in[2];   // [L, D]
    float* out = (float*)d_out;

    int B = in_sizes[0] / D;

    int grid = 148 * 5;                 // one wave at 5 CTAs/SM
    if (grid > B) grid = B;

    cross_fused<<<grid, TPB>>>(input, W, b, out, B);
}

// round 7
// speedup vs baseline: 1.2763x; 1.2763x over previous
#include <cuda_runtime.h>
#include <cuda_bf16.h>

// CrossNetwork (DCN-v1), closed form:
//   x_i = c_i * input + d_i
//   d_{i+1} = d_i + b_i ; e_i = d_i.w_i ; S_i = input.w_i (per-row)
//   c_{i+1} = c_i*(1+S_i) + e_i, c_0 = 1 ; out = c_L*input + d_L
//
// R7: latency attack. Batch 2 rows/iteration (interleaved shuffle chains,
// 1 barrier per 2 rows), R3 loop ordering (prefetch before bar, dependent
// combine after bar is LDS+FMA only), pick6 20-shfl reduce, float2-packed
// partials with uniform float4 combine serving both rows.

#define D    1024
#define L    6
#define TPB  128
#define NW   4            // warps per CTA

__device__ __forceinline__ float pick6(const float a[L], int i) {
    float s = a[0];
    s = (i == 1) ? a[1] : s;
    s = (i == 2) ? a[2] : s;
    s = (i == 3) ? a[3] : s;
    s = (i == 4) ? a[4] : s;
    s = (i == 5) ? a[5] : s;
    return s;
}

__global__ void __launch_bounds__(TPB, 4) cross_fused(const float* __restrict__ input,
                                                      const float* __restrict__ W,
                                                      const float* __restrict__ b,
                                                      float* __restrict__ out,
                                                      int B) {
    const int t = threadIdx.x;
    const int lane = t & 31, warp = t >> 5;
    const unsigned FULL = 0xFFFFFFFFu;

    // [parity][layer][warp*2 + rowInPair]; 8 floats per layer, 16B aligned
    __shared__ __align__(16) float red[2][L][NW * 2];

    // ---- W slice for this thread's 8 columns ----
    float4 wa[L], wb[L];
    #pragma unroll
    for (int l = 0; l < L; ++l) {
        wa[l] = __ldg(reinterpret_cast<const float4*>(W + l * D) + 2 * t);
        wb[l] = __ldg(reinterpret_cast<const float4*>(W + l * D) + 2 * t + 1);
    }

    // ---- Per-CTA prologue: d_L and e_l ----
    float4 da = make_float4(0.f, 0.f, 0.f, 0.f);
    float4 db = make_float4(0.f, 0.f, 0.f, 0.f);
    float pe[L];
    #pragma unroll
    for (int l = 0; l < L; ++l) {
        pe[l] = da.x * wa[l].x + da.y * wa[l].y + da.z * wa[l].z + da.w * wa[l].w
              + db.x * wb[l].x + db.y * wb[l].y + db.z * wb[l].z + db.w * wb[l].w;
        float4 ba = __ldg(reinterpret_cast<const float4*>(b + l * D) + 2 * t);
        float4 bb = __ldg(reinterpret_cast<const float4*>(b + l * D) + 2 * t + 1);
        da.x += ba.x; da.y += ba.y; da.z += ba.z; da.w += ba.w;
        db.x += bb.x; db.y += bb.y; db.z += bb.z; db.w += bb.w;
    }
    #pragma unroll
    for (int l = 0; l < L; ++l) {
        #pragma unroll
        for (int o = 16; o > 0; o >>= 1) pe[l] += __shfl_xor_sync(FULL, pe[l], o);
        if (lane == 0) red[0][l][warp] = pe[l];
    }
    __syncthreads();
    float e[L];
    #pragma unroll
    for (int l = 0; l < L; ++l) {
        float4 q = *reinterpret_cast<const float4*>(&red[0][l][0]);
        e[l] = (q.x + q.y) + (q.z + q.w);
    }
    __syncthreads();   // protect red[0] before loop reuse

    // ---- Grid-stride PAIR loop (rows 2k, 2k+1 always both valid: B even) ----
    const float4* in4  = reinterpret_cast<const float4*>(input);
    float4*       out4 = reinterpret_cast<float4*>(out);
    const int D4 = D / 4;
    const int rstep = 2 * gridDim.x;

    int r0 = 2 * blockIdx.x;
    if (r0 >= B) return;

    size_t base = (size_t)r0 * D4;
    float4 xa0 = in4[base + 2 * t];
    float4 xb0 = in4[base + 2 * t + 1];
    float4 xa1 = in4[base + D4 + 2 * t];
    float4 xb1 = in4[base + D4 + 2 * t + 1];

    int p = 0;
    for (; r0 < B; r0 += rstep, p ^= 1) {
        // ---- dots for both rows (independent chains) ----
        float acc0[L], acc1[L];
        #pragma unroll
        for (int l = 0; l < L; ++l) {
            acc0[l] = xa0.x * wa[l].x + xa0.y * wa[l].y + xa0.z * wa[l].z + xa0.w * wa[l].w
                    + xb0.x * wb[l].x + xb0.y * wb[l].y + xb0.z * wb[l].z + xb0.w * wb[l].w;
            acc1[l] = xa1.x * wa[l].x + xa1.y * wa[l].y + xa1.z * wa[l].z + xa1.w * wa[l].w
                    + xb1.x * wb[l].x + xb1.y * wb[l].y + xb1.z * wb[l].z + xb1.w * wb[l].w;
        }

        // ---- interleaved 3-stage butterflies ----
        #pragma unroll
        for (int l = 0; l < L; ++l) {
            acc0[l] += __shfl_xor_sync(FULL, acc0[l], 16);
            acc1[l] += __shfl_xor_sync(FULL, acc1[l], 16);
            acc0[l] += __shfl_xor_sync(FULL, acc0[l], 8);
            acc1[l] += __shfl_xor_sync(FULL, acc1[l], 8);
            acc0[l] += __shfl_xor_sync(FULL, acc0[l], 4);
            acc1[l] += __shfl_xor_sync(FULL, acc1[l], 4);
        }
        float v0 = pick6(acc0, lane >> 2);           // lane j: layer j>>2, class j&3
        float v1 = pick6(acc1, lane >> 2);
        v0 += __shfl_xor_sync(FULL, v0, 1);
        v1 += __shfl_xor_sync(FULL, v1, 1);
        v0 += __shfl_xor_sync(FULL, v0, 2);
        v1 += __shfl_xor_sync(FULL, v1, 2);
        if (lane < L * 4 && (lane & 3) == 0)
            *reinterpret_cast<float2*>(&red[p][lane >> 2][warp * 2]) = make_float2(v0, v1);

        // ---- prefetch next pair (overlaps barrier + combine) ----
        const int nr0 = r0 + rstep;
        float4 na0, nb0, na1, nb1;
        if (nr0 < B) {
            size_t nb_ = (size_t)nr0 * D4;
            na0 = in4[nb_ + 2 * t];
            nb0 = in4[nb_ + 2 * t + 1];
            na1 = in4[nb_ + D4 + 2 * t];
            nb1 = in4[nb_ + D4 + 2 * t + 1];
        }

        __syncthreads();

        // ---- combine: 2 uniform float4 per layer serve BOTH rows ----
        float c0 = 1.0f, c1 = 1.0f;
        #pragma unroll
        for (int l = 0; l < L; ++l) {
            float4 q0 = *reinterpret_cast<const float4*>(&red[p][l][0]); // w0r0 w0r1 w1r0 w1r1
            float4 q1 = *reinterpret_cast<const float4*>(&red[p][l][4]); // w2r0 w2r1 w3r0 w3r1
            float S0 = (q0.x + q0.z) + (q1.x + q1.z);
            float S1 = (q0.y + q0.w) + (q1.y + q1.w);
            c0 = fmaf(c0, 1.0f + S0, e[l]);
            c1 = fmaf(c1, 1.0f + S1, e[l]);
        }

        // ---- epilogue both rows ----
        float4 o0a, o0b, o1a, o1b;
        o0a.x = fmaf(c0, xa0.x, da.x); o0a.y = fmaf(c0, xa0.y, da.y);
        o0a.z = fmaf(c0, xa0.z, da.z); o0a.w = fmaf(c0, xa0.w, da.w);
        o0b.x = fmaf(c0, xb0.x, db.x); o0b.y = fmaf(c0, xb0.y, db.y);
        o0b.z = fmaf(c0, xb0.z, db.z); o0b.w = fmaf(c0, xb0.w, db.w);
        o1a.x = fmaf(c1, xa1.x, da.x); o1a.y = fmaf(c1, xa1.y, da.y);
        o1a.z = fmaf(c1, xa1.z, da.z); o1a.w = fmaf(c1, xa1.w, da.w);
        o1b.x = fmaf(c1, xb1.x, db.x); o1b.y = fmaf(c1, xb1.y, db.y);
        o1b.z = fmaf(c1, xb1.z, db.z); o1b.w = fmaf(c1, xb1.w, db.w);

        out4[base + 2 * t]          = o0a;
        out4[base + 2 * t + 1]      = o0b;
        out4[base + D4 + 2 * t]     = o1a;
        out4[base + D4 + 2 * t + 1] = o1b;

        xa0 = na0; xb0 = nb0; xa1 = na1; xb1 = nb1;
        base = (size_t)nr0 * D4;
    }
}

extern "C" void kernel_launch(void* const* d_in, const int* in_sizes, int n_in,
                              void* d_out, int out_size) {
    const float* input = (const float*)d_in[0];   // [B, D]
    const float* W     = (const float*)d_in[1];   // [L, D]
    const float* b     = (const float*)d_in[2];   // [L, D]
    float* out = (float*)d_out;

    int B = in_sizes[0] / D;

    int grid = 148 * 4;                 // one wave at 4 CTAs/SM (pair-per-CTA)
    int maxg = (B + 1) / 2;
    if (grid > maxg) grid = maxg;

    cross_fused<<<grid, TPB>>>(input, W, b, out, B);
}